// round 6
// baseline (speedup 1.0000x reference)
#include <cuda_runtime.h>
#include <cuda_bf16.h>
#include <cstdint>

// VectorQuantizer via mma.sync (HMMA bf16, split-precision), ILP-restructured:
// 2 independent accumulator chains, 32 tokens/warp (B-fragment reuse x2),
// exact-margin rescore for bit-exactness. B=32, D=64, T=8192, K=512.

#define BB 32
#define DD 64
#define TT 8192
#define KK 512
#define NTOK (BB * TT)
#define TILE_M 256
#define NTILES (NTOK / TILE_M)      // 1024
#define TILES_PER_B (TT / TILE_M)   // 32
#define NTHREADS 256
#define GRIDX 152
#define ARRSZ ((long long)BB * DD * TT)
#define MARGIN 5e-5f
#define FINF 3.402823466e38f

#define ROWS72 72
#define RSTRIDE (ROWS72 * 2)     // 144 B row stride (conflict-free ldmatrix)

// smem byte offsets
#define OFF_QN     0
#define OFF_REDF   32        // 8 f
#define OFF_REDK   64        // 8 i
#define OFF_E2     128       // 512 f  -> 2176
#define OFF_X2     2176      // 256 f  -> 3200
#define OFF_WIN    3200      // 256 i  -> 4224
#define OFF_QUE    4224      // 256 i  -> 5248
#define OFF_XH     5248      // 256*144 = 36864 -> 42112
#define OFF_XL     42112     // 36864 -> 78976
#define OFF_QS     OFF_XH    // overlay: 64*256*4 = 65536 <= 73728 (XH+XL)
#define OFF_EH     78976     // 512*144 = 73728 -> 152704
#define OFF_EL     152704    // 73728 -> 226432
#define SMEM_TOTAL 226432

__device__ __forceinline__ uint32_t smem_u32(const void* p) {
    uint32_t a;
    asm("{ .reg .u64 t; cvta.to.shared.u64 t, %1; cvt.u32.u64 %0, t; }" : "=r"(a) : "l"(p));
    return a;
}
__device__ __forceinline__ void ldsm_x4(uint32_t& r0, uint32_t& r1, uint32_t& r2, uint32_t& r3,
                                        uint32_t addr) {
    asm volatile("ldmatrix.sync.aligned.m8n8.x4.shared.b16 {%0,%1,%2,%3}, [%4];"
                 : "=r"(r0), "=r"(r1), "=r"(r2), "=r"(r3) : "r"(addr));
}
__device__ __forceinline__ void mma_bf16(float* c, const uint32_t* a, uint32_t b0, uint32_t b1) {
    asm volatile("mma.sync.aligned.m16n8k16.row.col.f32.bf16.bf16.f32 "
                 "{%0,%1,%2,%3}, {%4,%5,%6,%7}, {%8,%9}, {%0,%1,%2,%3};"
                 : "+f"(c[0]), "+f"(c[1]), "+f"(c[2]), "+f"(c[3])
                 : "r"(a[0]), "r"(a[1]), "r"(a[2]), "r"(a[3]), "r"(b0), "r"(b1));
}
__device__ __forceinline__ uint32_t pack_hi2(float v0, float v1, float& r0, float& r1) {
    __nv_bfloat16 h0 = __float2bfloat16_rn(v0);
    __nv_bfloat16 h1 = __float2bfloat16_rn(v1);
    r0 = __fsub_rn(v0, __bfloat162float(h0));
    r1 = __fsub_rn(v1, __bfloat162float(h1));
    return (uint32_t)__bfloat16_as_ushort(h0) | ((uint32_t)__bfloat16_as_ushort(h1) << 16);
}
__device__ __forceinline__ uint32_t pack_lo2(float r0, float r1) {
    __nv_bfloat16 l0 = __float2bfloat16_rn(r0);
    __nv_bfloat16 l1 = __float2bfloat16_rn(r1);
    return (uint32_t)__bfloat16_as_ushort(l0) | ((uint32_t)__bfloat16_as_ushort(l1) << 16);
}
// top-2 tracker update (ascending k order, strict <)
__device__ __forceinline__ void top2(float dd, int k, float& d1, float& d2, int& i1) {
    if (dd < d1) { d2 = d1; d1 = dd; i1 = k; }
    else if (dd < d2) { d2 = dd; }
}

extern __shared__ __align__(1024) char smem[];

__global__ void __launch_bounds__(NTHREADS, 1)
vq_mma_kernel(const float* __restrict__ x,
              const float* __restrict__ emb,
              float* __restrict__ out) {
    const int tid  = threadIdx.x;
    const int wid  = tid >> 5;
    const int lane = tid & 31;
    const uint32_t sb = smem_u32(smem);

    float* s_e2   = (float*)(smem + OFF_E2);
    float* s_x2   = (float*)(smem + OFF_X2);
    int*   s_win  = (int*)(smem + OFF_WIN);
    int*   s_que  = (int*)(smem + OFF_QUE);
    float* s_redf = (float*)(smem + OFF_REDF);
    int*   s_redk = (int*)(smem + OFF_REDK);
    int*   s_qn   = (int*)(smem + OFF_QN);
    float* q_s    = (float*)(smem + OFF_QS);

    // ---- Prologue: codebook -> exact e2 chain + bf16 split rows [512][72] ----
    for (int r = tid; r < KK; r += NTHREADS) {
        float ev[DD];
        const float4* er = (const float4*)(emb + r * DD);
        #pragma unroll
        for (int g = 0; g < DD / 4; g++) {
            float4 v = er[g];
            ev[g*4+0] = v.x; ev[g*4+1] = v.y; ev[g*4+2] = v.z; ev[g*4+3] = v.w;
        }
        float s = 0.0f;
        #pragma unroll
        for (int d = 0; d < DD; d++) s = __fadd_rn(s, __fmul_rn(ev[d], ev[d]));
        s_e2[r] = s;
        #pragma unroll
        for (int d = 0; d < DD; d += 2) {
            float r0, r1;
            uint32_t hp = pack_hi2(ev[d], ev[d+1], r0, r1);
            uint32_t lp = pack_lo2(r0, r1);
            *(uint32_t*)(smem + OFF_EH + r * RSTRIDE + d * 2) = hp;
            *(uint32_t*)(smem + OFF_EL + r * RSTRIDE + d * 2) = lp;
        }
    }

    float* o_st = out;
    float* o_q  = out + ARRSZ;

    const int lane4 = lane & 3;
    const int laneg = lane >> 2;
    const uint32_t a_off = (uint32_t)((lane & 15) * RSTRIDE + (lane >> 4) * 16);
    const uint32_t b_off = (uint32_t)((((lane & 7) + ((lane >> 4) << 3)) * RSTRIDE) +
                                      (((lane >> 3) & 1) * 16));

    for (int tile = blockIdx.x; tile < NTILES; tile += GRIDX) {
        const int b  = tile / TILES_PER_B;
        const int t0 = (tile % TILES_PER_B) * TILE_M;
        const float* xb = x + (long long)b * DD * TT + t0;
        const long long obase = (long long)b * DD * TT;

        // ---- Phase A: load x token (1/thread), exact x2 chain, bf16 split ----
        if (tid == 0) *s_qn = 0;
        {
            const int tt = tid;
            float xv[DD];
            #pragma unroll
            for (int d = 0; d < DD; d++) xv[d] = xb[(long long)d * TT + tt];
            float s = 0.0f;
            #pragma unroll
            for (int d = 0; d < DD; d++) s = __fadd_rn(s, __fmul_rn(xv[d], xv[d]));
            s_x2[tt] = s;
            #pragma unroll
            for (int d = 0; d < DD; d += 2) {
                float r0, r1;
                uint32_t hp = pack_hi2(xv[d], xv[d+1], r0, r1);
                uint32_t lp = pack_lo2(r0, r1);
                *(uint32_t*)(smem + OFF_XH + tt * RSTRIDE + d * 2) = hp;
                *(uint32_t*)(smem + OFF_XL + tt * RSTRIDE + d * 2) = lp;
            }
        }
        __syncthreads();

        // ---- Phase B: screen. warp w: tokens [32w, 32w+32), all 512 codes ----
        {
            const int m0 = wid * 32;
            uint32_t ah[2][4][4], al[2][4][4];
            #pragma unroll
            for (int g = 0; g < 2; g++) {
                const uint32_t abh = sb + OFF_XH + (m0 + g * 16) * RSTRIDE + a_off;
                const uint32_t abl = sb + OFF_XL + (m0 + g * 16) * RSTRIDE + a_off;
                #pragma unroll
                for (int s = 0; s < 4; s++) {
                    ldsm_x4(ah[g][s][0], ah[g][s][1], ah[g][s][2], ah[g][s][3], abh + s * 32);
                    ldsm_x4(al[g][s][0], al[g][s][1], al[g][s][2], al[g][s][3], abl + s * 32);
                }
            }

            // trackers: [g*2 + rowsel] ; rows: g0: laneg, laneg+8; g1: +16, +24
            float d1[4] = {FINF, FINF, FINF, FINF};
            float d2[4] = {FINF, FINF, FINF, FINF};
            int   i1[4] = {0, 0, 0, 0};

            const uint32_t bbh = sb + OFF_EH + b_off;
            const uint32_t bbl = sb + OFF_EL + b_off;

            for (int c = 0; c < 8; c++) {
                const int n0 = c * 64;
                #pragma unroll
                for (int p = 0; p < 4; p++) {
                    // two independent accumulator sets per group: hh | hl+lh
                    float a0[2][8], a1[2][8];
                    #pragma unroll
                    for (int g = 0; g < 2; g++)
                        #pragma unroll
                        for (int j = 0; j < 8; j++) { a0[g][j] = 0.f; a1[g][j] = 0.f; }

                    const uint32_t bth = bbh + (uint32_t)((n0 + 16 * p) * RSTRIDE);
                    const uint32_t btl = bbl + (uint32_t)((n0 + 16 * p) * RSTRIDE);
                    #pragma unroll
                    for (int s = 0; s < 4; s++) {
                        uint32_t h0, h1, h2, h3, l0, l1, l2, l3;
                        ldsm_x4(h0, h1, h2, h3, bth + s * 32);
                        ldsm_x4(l0, l1, l2, l3, btl + s * 32);
                        #pragma unroll
                        for (int g = 0; g < 2; g++) {
                            mma_bf16(a0[g],     ah[g][s], h0, h1);   // hh
                            mma_bf16(a0[g] + 4, ah[g][s], h2, h3);
                            mma_bf16(a1[g],     ah[g][s], l0, l1);   // hl
                            mma_bf16(a1[g] + 4, ah[g][s], l2, l3);
                            mma_bf16(a1[g],     al[g][s], h0, h1);   // lh
                            mma_bf16(a1[g] + 4, al[g][s], h2, h3);
                        }
                    }
                    const int cb0 = n0 + 16 * p + 2 * lane4;
                    const int cb1 = cb0 + 8;
                    const float e00 = s_e2[cb0], e01 = s_e2[cb0 + 1];
                    const float e10 = s_e2[cb1], e11 = s_e2[cb1 + 1];
                    #pragma unroll
                    for (int g = 0; g < 2; g++) {
                        float v;
                        v = __fadd_rn(a0[g][0], a1[g][0]);
                        top2(fmaf(-2.0f, v, e00), cb0,     d1[g*2],   d2[g*2],   i1[g*2]);
                        v = __fadd_rn(a0[g][1], a1[g][1]);
                        top2(fmaf(-2.0f, v, e01), cb0 + 1, d1[g*2],   d2[g*2],   i1[g*2]);
                        v = __fadd_rn(a0[g][2], a1[g][2]);
                        top2(fmaf(-2.0f, v, e00), cb0,     d1[g*2+1], d2[g*2+1], i1[g*2+1]);
                        v = __fadd_rn(a0[g][3], a1[g][3]);
                        top2(fmaf(-2.0f, v, e01), cb0 + 1, d1[g*2+1], d2[g*2+1], i1[g*2+1]);
                        v = __fadd_rn(a0[g][4], a1[g][4]);
                        top2(fmaf(-2.0f, v, e10), cb1,     d1[g*2],   d2[g*2],   i1[g*2]);
                        v = __fadd_rn(a0[g][5], a1[g][5]);
                        top2(fmaf(-2.0f, v, e11), cb1 + 1, d1[g*2],   d2[g*2],   i1[g*2]);
                        v = __fadd_rn(a0[g][6], a1[g][6]);
                        top2(fmaf(-2.0f, v, e10), cb1,     d1[g*2+1], d2[g*2+1], i1[g*2+1]);
                        v = __fadd_rn(a0[g][7], a1[g][7]);
                        top2(fmaf(-2.0f, v, e11), cb1 + 1, d1[g*2+1], d2[g*2+1], i1[g*2+1]);
                    }
                }
            }

            // quad reduce (lanes xor 1, 2), lexicographic (d, k), for 4 trackers
            #pragma unroll
            for (int m = 1; m <= 2; m <<= 1) {
                #pragma unroll
                for (int q = 0; q < 4; q++) {
                    float od = __shfl_xor_sync(0xffffffffu, d1[q], m);
                    int   oi = __shfl_xor_sync(0xffffffffu, i1[q], m);
                    float o2 = __shfl_xor_sync(0xffffffffu, d2[q], m);
                    bool take = (od < d1[q]) || (od == d1[q] && oi < i1[q]);
                    float nd2 = take ? fminf(d1[q], o2) : fminf(d2[q], od);
                    if (take) { d1[q] = od; i1[q] = oi; }
                    d2[q] = nd2;
                }
            }
            if (lane4 == 0) {
                #pragma unroll
                for (int q = 0; q < 4; q++) {
                    // q -> row: g = q>>1, rowsel = q&1 -> m0 + g*16 + rowsel*8 + laneg
                    const int row = m0 + (q >> 1) * 16 + (q & 1) * 8 + laneg;
                    s_win[row] = i1[q];
                    if (!(d2[q] - d1[q] > MARGIN)) {
                        int qq = atomicAdd(s_qn, 1);
                        s_que[qq] = row;
                    }
                }
            }
        }
        __syncthreads();

        // ---- Phase E: exact rescore (reference chain) for ambiguous tokens ----
        {
            const int nq = *s_qn;
            for (int j = 0; j < nq; j++) {
                const int tt = s_que[j];
                const float x2t = s_x2[tt];
                // broadcast-load x for this token from gmem (L2-hot)
                float xr[DD];
                #pragma unroll
                for (int d = 0; d < DD; d++)
                    xr[d] = __ldg(xb + (long long)d * TT + tt);
                float bd; int bk;
                {
                    const int k0 = tid, k1 = tid + 256;
                    const float4* e0 = (const float4*)(emb + k0 * DD);
                    const float4* e1 = (const float4*)(emb + k1 * DD);
                    float s0 = 0.0f, s1 = 0.0f;
                    #pragma unroll
                    for (int g = 0; g < DD / 4; g++) {
                        float4 v0 = __ldg(e0 + g);
                        float4 v1 = __ldg(e1 + g);
                        s0 = fmaf(xr[g*4+0], v0.x, s0); s0 = fmaf(xr[g*4+1], v0.y, s0);
                        s0 = fmaf(xr[g*4+2], v0.z, s0); s0 = fmaf(xr[g*4+3], v0.w, s0);
                        s1 = fmaf(xr[g*4+0], v1.x, s1); s1 = fmaf(xr[g*4+1], v1.y, s1);
                        s1 = fmaf(xr[g*4+2], v1.z, s1); s1 = fmaf(xr[g*4+3], v1.w, s1);
                    }
                    float dA = __fadd_rn(__fsub_rn(x2t, 2.0f * s0), s_e2[k0]);
                    float dB = __fadd_rn(__fsub_rn(x2t, 2.0f * s1), s_e2[k1]);
                    bd = dA; bk = k0;
                    if (dB < bd) { bd = dB; bk = k1; }
                }
                #pragma unroll
                for (int off = 16; off; off >>= 1) {
                    float od = __shfl_down_sync(0xFFFFFFFFu, bd, off);
                    int   ok = __shfl_down_sync(0xFFFFFFFFu, bk, off);
                    if (od < bd || (od == bd && ok < bk)) { bd = od; bk = ok; }
                }
                if (lane == 0) { s_redf[wid] = bd; s_redk[wid] = bk; }
                __syncthreads();
                if (tid == 0) {
                    float fb = s_redf[0]; int fk = s_redk[0];
                    #pragma unroll
                    for (int w = 1; w < 8; w++) {
                        float od = s_redf[w]; int ok = s_redk[w];
                        if (od < fb || (od == fb && ok < fk)) { fb = od; fk = ok; }
                    }
                    s_win[tt] = fk;
                }
                __syncthreads();
            }
        }

        // ---- Phase F: gather q rows (overlay XH/XL), then coalesced writes ----
        {
            const int tt = tid;
            const int k = s_win[tt];
            const float4* er = (const float4*)(emb + k * DD);
            #pragma unroll
            for (int g = 0; g < DD / 4; g++) {
                float4 v = __ldg(er + g);
                q_s[(g*4+0) * TILE_M + tt] = v.x;
                q_s[(g*4+1) * TILE_M + tt] = v.y;
                q_s[(g*4+2) * TILE_M + tt] = v.z;
                q_s[(g*4+3) * TILE_M + tt] = v.w;
            }
        }
        __syncthreads();
        {
            #pragma unroll
            for (int it = 0; it < (DD * TILE_M / 2) / NTHREADS; it++) {
                const int item = tid + it * NTHREADS;
                const int d = item >> 7;          // 0..63
                const int p = item & 127;         // 0..127
                const int ti = p * 2;
                float q0 = q_s[d * TILE_M + ti];
                float q1 = q_s[d * TILE_M + ti + 1];
                const float2 xv = *(const float2*)(xb + (long long)d * TT + ti);
                float2 stv = make_float2(__fadd_rn(xv.x, __fsub_rn(q0, xv.x)),
                                         __fadd_rn(xv.y, __fsub_rn(q1, xv.y)));
                float2 qv = make_float2(q0, q1);
                const long long o = obase + (long long)d * TT + t0 + ti;
                *(float2*)(o_st + o) = stv;
                *(float2*)(o_q + o)  = qv;
            }
        }
        __syncthreads();
    }
}

extern "C" void kernel_launch(void* const* d_in, const int* in_sizes, int n_in,
                              void* d_out, int out_size) {
    const float* x   = (const float*)d_in[0];
    const float* emb = (const float*)d_in[1];
    float* out = (float*)d_out;
    (void)in_sizes; (void)n_in; (void)out_size;

    cudaFuncSetAttribute(vq_mma_kernel,
                         cudaFuncAttributeMaxDynamicSharedMemorySize, SMEM_TOTAL);
    vq_mma_kernel<<<GRIDX, NTHREADS, SMEM_TOTAL>>>(x, emb, out);
}

// round 7
// speedup vs baseline: 1.2290x; 1.2290x over previous
#include <cuda_runtime.h>
#include <cuda_bf16.h>
#include <cstdint>

// VectorQuantizer via mma.sync (HMMA bf16, split-precision).
// 16 warps: warp w screens 16 tokens x half the codebook; halves merged in smem.
// Split accumulator chains (hh | hl+lh) for shorter dependency chains.
// Exact-margin rescore keeps bit-exactness. B=32, D=64, T=8192, K=512.

#define BB 32
#define DD 64
#define TT 8192
#define KK 512
#define NTOK (BB * TT)
#define TILE_M 128
#define NTILES (NTOK / TILE_M)      // 2048
#define TILES_PER_B (TT / TILE_M)   // 64
#define NTHREADS 512
#define NWARP 16
#define GRIDX 152
#define ARRSZ ((long long)BB * DD * TT)
#define MARGIN 5e-5f
#define FINF 3.402823466e38f

#define ROWS72 72
#define RSTRIDE (ROWS72 * 2)     // 144 B row stride (conflict-free ldmatrix)

// smem byte offsets
#define OFF_QN     0
#define OFF_REDF   32        // 16 f -> 96
#define OFF_REDK   96        // 16 i -> 160
#define OFF_E2     160       // 512 f -> 2208
#define OFF_X2     2208      // 128 f -> 2720
#define OFF_WIN    2720      // 128 i -> 3232
#define OFF_QUE    3232      // 128 i -> 3744
#define OFF_D1     3744      // 256 f -> 4768
#define OFF_I1     4768      // 256 i -> 5792
#define OFF_D2     5792      // 256 f -> 6816
#define OFF_XH     7168      // 128*144 = 18432 -> 25600
#define OFF_XL     25600     // 18432 -> 44032
#define OFF_QS     OFF_XH    // overlay: 64*128*4 = 32768 <= 36864 (XH+XL)
#define OFF_EH     44032     // 512*144 = 73728 -> 117760
#define OFF_EL     117760    // 73728 -> 191488
#define SMEM_TOTAL 191488

__device__ __forceinline__ uint32_t smem_u32(const void* p) {
    uint32_t a;
    asm("{ .reg .u64 t; cvta.to.shared.u64 t, %1; cvt.u32.u64 %0, t; }" : "=r"(a) : "l"(p));
    return a;
}
__device__ __forceinline__ void ldsm_x4(uint32_t& r0, uint32_t& r1, uint32_t& r2, uint32_t& r3,
                                        uint32_t addr) {
    asm volatile("ldmatrix.sync.aligned.m8n8.x4.shared.b16 {%0,%1,%2,%3}, [%4];"
                 : "=r"(r0), "=r"(r1), "=r"(r2), "=r"(r3) : "r"(addr));
}
__device__ __forceinline__ void mma_bf16(float* c, const uint32_t* a, uint32_t b0, uint32_t b1) {
    asm volatile("mma.sync.aligned.m16n8k16.row.col.f32.bf16.bf16.f32 "
                 "{%0,%1,%2,%3}, {%4,%5,%6,%7}, {%8,%9}, {%0,%1,%2,%3};"
                 : "+f"(c[0]), "+f"(c[1]), "+f"(c[2]), "+f"(c[3])
                 : "r"(a[0]), "r"(a[1]), "r"(a[2]), "r"(a[3]), "r"(b0), "r"(b1));
}
__device__ __forceinline__ uint32_t pack_hi2(float v0, float v1, float& r0, float& r1) {
    __nv_bfloat16 h0 = __float2bfloat16_rn(v0);
    __nv_bfloat16 h1 = __float2bfloat16_rn(v1);
    r0 = __fsub_rn(v0, __bfloat162float(h0));
    r1 = __fsub_rn(v1, __bfloat162float(h1));
    return (uint32_t)__bfloat16_as_ushort(h0) | ((uint32_t)__bfloat16_as_ushort(h1) << 16);
}
__device__ __forceinline__ uint32_t pack_lo2(float r0, float r1) {
    __nv_bfloat16 l0 = __float2bfloat16_rn(r0);
    __nv_bfloat16 l1 = __float2bfloat16_rn(r1);
    return (uint32_t)__bfloat16_as_ushort(l0) | ((uint32_t)__bfloat16_as_ushort(l1) << 16);
}
__device__ __forceinline__ void top2(float dd, int k, float& d1, float& d2, int& i1) {
    if (dd < d1) { d2 = d1; d1 = dd; i1 = k; }
    else if (dd < d2) { d2 = dd; }
}

extern __shared__ __align__(1024) char smem[];

__global__ void __launch_bounds__(NTHREADS, 1)
vq_mma_kernel(const float* __restrict__ x,
              const float* __restrict__ emb,
              float* __restrict__ out) {
    const int tid  = threadIdx.x;
    const int wid  = tid >> 5;
    const int lane = tid & 31;
    const uint32_t sb = smem_u32(smem);

    float* s_e2   = (float*)(smem + OFF_E2);
    float* s_x2   = (float*)(smem + OFF_X2);
    int*   s_win  = (int*)(smem + OFF_WIN);
    int*   s_que  = (int*)(smem + OFF_QUE);
    float* s_d1   = (float*)(smem + OFF_D1);
    int*   s_i1   = (int*)(smem + OFF_I1);
    float* s_d2   = (float*)(smem + OFF_D2);
    float* s_redf = (float*)(smem + OFF_REDF);
    int*   s_redk = (int*)(smem + OFF_REDK);
    int*   s_qn   = (int*)(smem + OFF_QN);
    float* q_s    = (float*)(smem + OFF_QS);

    // ---- Prologue: codebook -> exact e2 chain + bf16 split rows [512][72] ----
    for (int r = tid; r < KK; r += NTHREADS) {
        float ev[DD];
        const float4* er = (const float4*)(emb + r * DD);
        #pragma unroll
        for (int g = 0; g < DD / 4; g++) {
            float4 v = er[g];
            ev[g*4+0] = v.x; ev[g*4+1] = v.y; ev[g*4+2] = v.z; ev[g*4+3] = v.w;
        }
        float s = 0.0f;
        #pragma unroll
        for (int d = 0; d < DD; d++) s = __fadd_rn(s, __fmul_rn(ev[d], ev[d]));
        s_e2[r] = s;
        #pragma unroll
        for (int d = 0; d < DD; d += 2) {
            float r0, r1;
            uint32_t hp = pack_hi2(ev[d], ev[d+1], r0, r1);
            uint32_t lp = pack_lo2(r0, r1);
            *(uint32_t*)(smem + OFF_EH + r * RSTRIDE + d * 2) = hp;
            *(uint32_t*)(smem + OFF_EL + r * RSTRIDE + d * 2) = lp;
        }
    }

    float* o_st = out;
    float* o_q  = out + ARRSZ;

    const int lane4 = lane & 3;
    const int laneg = lane >> 2;
    const uint32_t a_off = (uint32_t)((lane & 15) * RSTRIDE + (lane >> 4) * 16);
    const uint32_t b_off = (uint32_t)((((lane & 7) + ((lane >> 4) << 3)) * RSTRIDE) +
                                      (((lane >> 3) & 1) * 16));

    for (int tile = blockIdx.x; tile < NTILES; tile += GRIDX) {
        const int b  = tile / TILES_PER_B;
        const int t0 = (tile % TILES_PER_B) * TILE_M;
        const float* xb = x + (long long)b * DD * TT + t0;
        const long long obase = (long long)b * DD * TT;

        // ---- Phase A: load x (threads 0..127), exact x2 chain, bf16 split ----
        if (tid == 0) *s_qn = 0;
        if (tid < TILE_M) {
            const int tt = tid;
            float xv[DD];
            #pragma unroll
            for (int d = 0; d < DD; d++) xv[d] = xb[(long long)d * TT + tt];
            float s = 0.0f;
            #pragma unroll
            for (int d = 0; d < DD; d++) s = __fadd_rn(s, __fmul_rn(xv[d], xv[d]));
            s_x2[tt] = s;
            #pragma unroll
            for (int d = 0; d < DD; d += 2) {
                float r0, r1;
                uint32_t hp = pack_hi2(xv[d], xv[d+1], r0, r1);
                uint32_t lp = pack_lo2(r0, r1);
                *(uint32_t*)(smem + OFF_XH + tt * RSTRIDE + d * 2) = hp;
                *(uint32_t*)(smem + OFF_XL + tt * RSTRIDE + d * 2) = lp;
            }
        }
        __syncthreads();

        // ---- Phase B: screen. warp w: tokens [16*(w&7), +16), codes half=(w>>3) ----
        {
            const int half = wid >> 3;          // 0 or 1
            const int m0   = (wid & 7) * 16;
            const int k0g  = half * 256;        // code range base
            uint32_t ah[4][4], al[4][4];
            const uint32_t abh = sb + OFF_XH + m0 * RSTRIDE + a_off;
            const uint32_t abl = sb + OFF_XL + m0 * RSTRIDE + a_off;
            #pragma unroll
            for (int s = 0; s < 4; s++) {
                ldsm_x4(ah[s][0], ah[s][1], ah[s][2], ah[s][3], abh + s * 32);
                ldsm_x4(al[s][0], al[s][1], al[s][2], al[s][3], abl + s * 32);
            }

            float d1a = FINF, d2a = FINF, d1b = FINF, d2b = FINF;
            int   i1a = k0g, i1b = k0g;
            const uint32_t bbh = sb + OFF_EH + (uint32_t)(k0g * RSTRIDE) + b_off;
            const uint32_t bbl = sb + OFF_EL + (uint32_t)(k0g * RSTRIDE) + b_off;

            for (int c = 0; c < 4; c++) {
                const int n0 = c * 64;
                #pragma unroll
                for (int p = 0; p < 4; p++) {
                    // split chains: a0 = hh ; a1 = hl + lh
                    float a0[8], a1[8];
                    #pragma unroll
                    for (int j = 0; j < 8; j++) { a0[j] = 0.f; a1[j] = 0.f; }
                    const uint32_t bth = bbh + (uint32_t)((n0 + 16 * p) * RSTRIDE);
                    const uint32_t btl = bbl + (uint32_t)((n0 + 16 * p) * RSTRIDE);
                    #pragma unroll
                    for (int s = 0; s < 4; s++) {
                        uint32_t h0, h1, h2, h3, l0, l1, l2, l3;
                        ldsm_x4(h0, h1, h2, h3, bth + s * 32);
                        ldsm_x4(l0, l1, l2, l3, btl + s * 32);
                        mma_bf16(a0,     ah[s], h0, h1);   // hh
                        mma_bf16(a0 + 4, ah[s], h2, h3);
                        mma_bf16(a1,     ah[s], l0, l1);   // hl
                        mma_bf16(a1 + 4, ah[s], l2, l3);
                        mma_bf16(a1,     al[s], h0, h1);   // lh
                        mma_bf16(a1 + 4, al[s], h2, h3);
                    }
                    const int cb0 = k0g + n0 + 16 * p + 2 * lane4;
                    const int cb1 = cb0 + 8;
                    const float e00 = s_e2[cb0], e01 = s_e2[cb0 + 1];
                    const float e10 = s_e2[cb1], e11 = s_e2[cb1 + 1];
                    float v;
                    v = __fadd_rn(a0[0], a1[0]);
                    top2(fmaf(-2.0f, v, e00), cb0,     d1a, d2a, i1a);
                    v = __fadd_rn(a0[1], a1[1]);
                    top2(fmaf(-2.0f, v, e01), cb0 + 1, d1a, d2a, i1a);
                    v = __fadd_rn(a0[2], a1[2]);
                    top2(fmaf(-2.0f, v, e00), cb0,     d1b, d2b, i1b);
                    v = __fadd_rn(a0[3], a1[3]);
                    top2(fmaf(-2.0f, v, e01), cb0 + 1, d1b, d2b, i1b);
                    v = __fadd_rn(a0[4], a1[4]);
                    top2(fmaf(-2.0f, v, e10), cb1,     d1a, d2a, i1a);
                    v = __fadd_rn(a0[5], a1[5]);
                    top2(fmaf(-2.0f, v, e11), cb1 + 1, d1a, d2a, i1a);
                    v = __fadd_rn(a0[6], a1[6]);
                    top2(fmaf(-2.0f, v, e10), cb1,     d1b, d2b, i1b);
                    v = __fadd_rn(a0[7], a1[7]);
                    top2(fmaf(-2.0f, v, e11), cb1 + 1, d1b, d2b, i1b);
                }
            }

            // quad reduce (lanes xor 1, 2) lexicographic (d, k)
            #pragma unroll
            for (int m = 1; m <= 2; m <<= 1) {
                float od = __shfl_xor_sync(0xffffffffu, d1a, m);
                int   oi = __shfl_xor_sync(0xffffffffu, i1a, m);
                float o2 = __shfl_xor_sync(0xffffffffu, d2a, m);
                bool take = (od < d1a) || (od == d1a && oi < i1a);
                float nd2 = take ? fminf(d1a, o2) : fminf(d2a, od);
                if (take) { d1a = od; i1a = oi; }
                d2a = nd2;
                od = __shfl_xor_sync(0xffffffffu, d1b, m);
                oi = __shfl_xor_sync(0xffffffffu, i1b, m);
                o2 = __shfl_xor_sync(0xffffffffu, d2b, m);
                take = (od < d1b) || (od == d1b && oi < i1b);
                nd2 = take ? fminf(d1b, o2) : fminf(d2b, od);
                if (take) { d1b = od; i1b = oi; }
                d2b = nd2;
            }
            if (lane4 == 0) {
                const int r0 = m0 + laneg, r1 = r0 + 8;
                s_d1[half * 128 + r0] = d1a;
                s_i1[half * 128 + r0] = i1a;
                s_d2[half * 128 + r0] = d2a;
                s_d1[half * 128 + r1] = d1b;
                s_i1[half * 128 + r1] = i1b;
                s_d2[half * 128 + r1] = d2b;
            }
        }
        __syncthreads();

        // ---- Phase D: merge halves + margin test + queue ----
        if (tid < TILE_M) {
            const int tt = tid;
            float d1a = s_d1[tt],       d2a = s_d2[tt];       int i1a = s_i1[tt];
            float d1b = s_d1[128 + tt], d2b = s_d2[128 + tt]; int i1b = s_i1[128 + tt];
            float D1, D2; int I1;
            if (d1b < d1a) { D1 = d1b; I1 = i1b; D2 = fminf(d1a, d2b); }
            else           { D1 = d1a; I1 = i1a; D2 = fminf(d2a, d1b); }
            s_win[tt] = I1;
            if (!(D2 - D1 > MARGIN)) {
                int qi = atomicAdd(s_qn, 1);
                s_que[qi] = tt;
            }
        }
        __syncthreads();

        // ---- Phase E: exact rescore (reference chain) for ambiguous tokens ----
        {
            const int nq = *s_qn;
            for (int j = 0; j < nq; j++) {
                const int tt = s_que[j];
                const float x2t = s_x2[tt];
                float xr[DD];
                #pragma unroll
                for (int d = 0; d < DD; d++)
                    xr[d] = __ldg(xb + (long long)d * TT + tt);
                float bd; int bk;
                {
                    const int k0 = tid;           // 512 threads = 512 codes
                    const float4* e0 = (const float4*)(emb + k0 * DD);
                    float s0 = 0.0f;
                    #pragma unroll
                    for (int g = 0; g < DD / 4; g++) {
                        float4 v0 = __ldg(e0 + g);
                        s0 = fmaf(xr[g*4+0], v0.x, s0); s0 = fmaf(xr[g*4+1], v0.y, s0);
                        s0 = fmaf(xr[g*4+2], v0.z, s0); s0 = fmaf(xr[g*4+3], v0.w, s0);
                    }
                    bd = __fadd_rn(__fsub_rn(x2t, 2.0f * s0), s_e2[k0]);
                    bk = k0;
                }
                #pragma unroll
                for (int off = 16; off; off >>= 1) {
                    float od = __shfl_down_sync(0xFFFFFFFFu, bd, off);
                    int   ok = __shfl_down_sync(0xFFFFFFFFu, bk, off);
                    if (od < bd || (od == bd && ok < bk)) { bd = od; bk = ok; }
                }
                if (lane == 0) { s_redf[wid] = bd; s_redk[wid] = bk; }
                __syncthreads();
                if (tid == 0) {
                    float fb = s_redf[0]; int fk = s_redk[0];
                    #pragma unroll
                    for (int w = 1; w < NWARP; w++) {
                        float od = s_redf[w]; int ok = s_redk[w];
                        if (od < fb || (od == fb && ok < fk)) { fb = od; fk = ok; }
                    }
                    s_win[tt] = fk;
                }
                __syncthreads();
            }
        }

        // ---- Phase F: gather q rows (overlay XH/XL), then coalesced writes ----
        if (tid < TILE_M) {
            const int tt = tid;
            const int k = s_win[tt];
            const float4* er = (const float4*)(emb + k * DD);
            #pragma unroll
            for (int g = 0; g < DD / 4; g++) {
                float4 v = __ldg(er + g);
                q_s[(g*4+0) * TILE_M + tt] = v.x;
                q_s[(g*4+1) * TILE_M + tt] = v.y;
                q_s[(g*4+2) * TILE_M + tt] = v.z;
                q_s[(g*4+3) * TILE_M + tt] = v.w;
            }
        }
        __syncthreads();
        {
            #pragma unroll
            for (int it = 0; it < (DD * TILE_M / 2) / NTHREADS; it++) {
                const int item = tid + it * NTHREADS;
                const int d = item >> 6;          // 0..63
                const int p = item & 63;          // 0..63
                const int ti = p * 2;
                float q0 = q_s[d * TILE_M + ti];
                float q1 = q_s[d * TILE_M + ti + 1];
                const float2 xv = *(const float2*)(xb + (long long)d * TT + ti);
                float2 stv = make_float2(__fadd_rn(xv.x, __fsub_rn(q0, xv.x)),
                                         __fadd_rn(xv.y, __fsub_rn(q1, xv.y)));
                float2 qv = make_float2(q0, q1);
                const long long o = obase + (long long)d * TT + t0 + ti;
                *(float2*)(o_st + o) = stv;
                *(float2*)(o_q + o)  = qv;
            }
        }
        __syncthreads();
    }
}

extern "C" void kernel_launch(void* const* d_in, const int* in_sizes, int n_in,
                              void* d_out, int out_size) {
    const float* x   = (const float*)d_in[0];
    const float* emb = (const float*)d_in[1];
    float* out = (float*)d_out;
    (void)in_sizes; (void)n_in; (void)out_size;

    cudaFuncSetAttribute(vq_mma_kernel,
                         cudaFuncAttributeMaxDynamicSharedMemorySize, SMEM_TOTAL);
    vq_mma_kernel<<<GRIDX, NTHREADS, SMEM_TOTAL>>>(x, emb, out);
}